// round 3
// baseline (speedup 1.0000x reference)
#include <cuda_runtime.h>
#include <math.h>

// ---------------- problem constants ----------------
#define B_      1024
#define T_      256
#define DIN_    128
#define INTER_  269
#define CMD_    179
#define MOTOR_  64
#define OUT_    64
#define UNITS_  512
#define CAT0    (DIN_ + INTER_)   // 397
#define CAT1    (INTER_ + CMD_)   // 448
#define CAT2    (CMD_ + MOTOR_)   // 243

#define MBC     16                // batch rows per CLUSTER (shared by 2 CTAs)
#define CSIZE   2
#define NGRP    (B_ / MBC)        // 64 groups
#define NBLK    (NGRP * CSIZE)    // 128 CTAs
#define NTHR    384

#define XS      20                // xc row stride (floats), 16B-aligned sublanes
#define PS      20                // partial slot stride (floats)

// tasks = NH * 4(bq) * KC
#define KC0     1
#define KC1     1
#define KC2     3
#define TASKS0  (INTER_ * 4 * KC0)   // 1076
#define TASKS1  (CMD_   * 4 * KC1)   // 716
#define TASKS2  (MOTOR_ * 4 * KC2)   // 768
#define MAXTASK TASKS0

#define P0_ (CAT0 * INTER_)
#define P1_ (CAT1 * CMD_)
#define P2_ (CAT2 * MOTOR_)
#define PTOT_ (P0_ + P1_ + P2_)

// exchange buffer (canonical partials) per CTA
#define EX_L0   0
#define EX_L1   (INTER_ * 64)                 // 17216
#define EX_L2   (EX_L1 + CMD_ * 64)           // 28672
#define EXSZ    (EX_L2 + MOTOR_ * 64)         // 32768

// ---------------- device scratch (static, allowed) ----------------
__device__ __align__(16) float g_wt0[P0_ * 4];
__device__ __align__(16) float g_wt1[P1_ * 4];
__device__ __align__(16) float g_wt2[P2_ * 4];
__device__ __align__(16) float g_ex[NBLK * EXSZ];

struct Params {
    const float* x;
    const float* hidden;
    const void*  mask0;
    const void*  mask1;
    const void*  mask2;
    const float* w0[4]; const float* b0[4];   // ff1, ff2, ta, tb
    const float* w1[4]; const float* b1[4];
    const float* w2[4]; const float* b2[4];
    const float* fc_w;  const float* fc_b;
    float* out;
};

// ---------------- mask dtype helpers ----------------
__device__ __forceinline__ float mask_val(const void* mp, int mode, int e) {
    if (mode == 0) return ((const unsigned char*)mp)[e] ? 1.0f : 0.0f;
    if (mode == 1) return ((const int*)mp)[e] ? 1.0f : 0.0f;
    return (((const float*)mp)[e] != 0.0f) ? 1.0f : 0.0f;
}

// ---------------- prep: inline sniff + masked transposed gate-quad weights ----------------
// wt[k*NH + j] = float4{ff1*m, ff2*m, ta, tb}
__global__ void prep_kernel(Params P) {
    __shared__ int smode[3];
    {
        int w = threadIdx.x >> 5, lane = threadIdx.x & 31;
        if (w < 3) {
            const unsigned char* p = (const unsigned char*)
                (w == 0 ? P.mask0 : (w == 1 ? P.mask1 : P.mask2));
            int nz = 0, gt = 0;
            for (int i = lane; i < 4096; i += 32) {
                unsigned char v = p[i];
                nz += (v != 0);
                gt |= (v > 1);
            }
            nz = __reduce_add_sync(0xffffffffu, nz);
            gt = __reduce_or_sync(0xffffffffu, gt);
            if (lane == 0) smode[w] = gt ? 2 : (nz > 2048 ? 0 : 1);
        }
    }
    __syncthreads();

    int p = blockIdx.x * blockDim.x + threadIdx.x;
    if (p >= PTOT_) return;

    int NH, CATL, local, mode;
    float* wt;
    const float* const* ws;
    const void* mp;
    if (p < P0_) {
        local = p; NH = INTER_; CATL = CAT0; wt = g_wt0;
        ws = P.w0; mp = P.mask0; mode = smode[0];
    } else if (p < P0_ + P1_) {
        local = p - P0_; NH = CMD_; CATL = CAT1; wt = g_wt1;
        ws = P.w1; mp = P.mask1; mode = smode[1];
    } else {
        local = p - P0_ - P1_; NH = MOTOR_; CATL = CAT2; wt = g_wt2;
        ws = P.w2; mp = P.mask2; mode = smode[2];
    }
    int k = local / NH;
    int j = local - k * NH;
    int we = j * CATL + k;
    float m = mask_val(mp, mode, we);
    float4 v;
    v.x = ws[0][we] * m;
    v.y = ws[1][we] * m;
    v.z = ws[2][we];
    v.w = ws[3][we];
    *(float4*)(wt + (size_t)local * 4) = v;
}

// ---------------- packed f32x2 helpers ----------------
__device__ __forceinline__ unsigned long long pack2(float w) {
    unsigned long long r;
    asm("mov.b64 %0, {%1, %1};" : "=l"(r) : "f"(w));
    return r;
}
#define FFMA2(acc, w2, x2) \
    asm("fma.rn.f32x2 %0, %1, %2, %0;" : "+l"(acc) : "l"(w2), "l"(x2))

__device__ __forceinline__ float ldcg(const float* p) {
    float v;
    asm volatile("ld.global.cg.f32 %0, [%1];" : "=f"(v) : "l"(p));
    return v;
}

#define CLUSTER_ARRIVE() asm volatile("barrier.cluster.arrive.aligned;" ::: "memory")
#define CLUSTER_WAIT()   asm volatile("barrier.cluster.wait.aligned;" ::: "memory")

// ---------------- gates: thread = (j, batch-quarter, kc) over this CTA's k-half ----------------
template <int NH, int KC>
__device__ __forceinline__ void gates(const float4* __restrict__ wt,
                                      const float* __restrict__ xc,
                                      float* __restrict__ part,
                                      int k0, int kh, int tid) {
    const int TASKS = NH * 4 * KC;
    for (int idx = tid; idx < TASKS; idx += NTHR) {
        int j = idx % NH;
        int q = idx / NH;
        int bq = q & 3, kc = q >> 2;
        int ka = (kh * kc) / KC;
        int kb = (kh * (kc + 1)) / KC;
        const float4* w = wt + (size_t)(k0 + ka) * NH + j;
        const float* xp = xc + ka * XS + bq * 4;
        unsigned long long a0 = 0, a1 = 0, a2 = 0, a3 = 0,
                           a4 = 0, a5 = 0, a6 = 0, a7 = 0;
#pragma unroll 4
        for (int kk = ka; kk < kb; ++kk) {
            float4 wv = __ldg(w);
            w += NH;
            ulonglong2 xv = *(const ulonglong2*)xp;
            xp += XS;
            unsigned long long wA = pack2(wv.x);
            unsigned long long wB = pack2(wv.y);
            unsigned long long wC = pack2(wv.z);
            unsigned long long wD = pack2(wv.w);
            FFMA2(a0, wA, xv.x); FFMA2(a1, wA, xv.y);
            FFMA2(a2, wB, xv.x); FFMA2(a3, wB, xv.y);
            FFMA2(a4, wC, xv.x); FFMA2(a5, wC, xv.y);
            FFMA2(a6, wD, xv.x); FFMA2(a7, wD, xv.y);
        }
        float* pp = part + idx * PS;
        ulonglong2 s;
        s.x = a0; s.y = a1; *(ulonglong2*)(pp + 0)  = s;
        s.x = a2; s.y = a3; *(ulonglong2*)(pp + 4)  = s;
        s.x = a4; s.y = a5; *(ulonglong2*)(pp + 8)  = s;
        s.x = a6; s.y = a7; *(ulonglong2*)(pp + 12) = s;
    }
}

// canonical partial for my k-half -> gmem (layout it = j*64 + g*16 + b)
template <int NH, int KC>
__device__ __forceinline__ void phaseA(const float* __restrict__ part,
                                       float* __restrict__ exMy, int tid) {
    for (int it = tid; it < NH * 64; it += NTHR) {
        int j = it >> 6, r = it & 63;
        int g = r >> 4, b = r & 15;
        int bq = b >> 2, bl = b & 3;
        float v = 0.f;
#pragma unroll
        for (int kc = 0; kc < KC; ++kc)
            v += part[((kc * 4 + bq) * NH + j) * PS + g * 4 + bl];
        exMy[it] = v;
    }
}

// combine my partials + peer partials -> activations -> h
template <int NH, int KC>
__device__ __forceinline__ void phaseB(const float* __restrict__ part,
                                       const float* __restrict__ exPeer,
                                       const float* __restrict__ bias,
                                       float* __restrict__ h, int tid) {
    for (int it = tid; it < NH * 16; it += NTHR) {
        int j = it >> 4, b = it & 15;
        int bq = b >> 2, bl = b & 3;
        float s[4];
#pragma unroll
        for (int g = 0; g < 4; ++g) {
            float v = ldcg(exPeer + j * 64 + g * 16 + b);
#pragma unroll
            for (int kc = 0; kc < KC; ++kc)
                v += part[((kc * 4 + bq) * NH + j) * PS + g * 4 + bl];
            s[g] = v;
        }
        float ff1 = tanhf(s[0] + bias[j * 4 + 0]);
        float ff2 = tanhf(s[1] + bias[j * 4 + 1]);
        float z = s[2] + bias[j * 4 + 2] + s[3] + bias[j * 4 + 3];
        float sg = 1.0f / (1.0f + __expf(-z));
        h[it] = ff1 + sg * (ff2 - ff1);
    }
}

// copy h segment into local xc window: global-k segment [lo,hi) of seg starting segStart
__device__ __forceinline__ void stage_h(float* __restrict__ xc, int k0,
                                        int lo, int hi, int segStart,
                                        const float* __restrict__ src, int tid) {
    int n = hi - lo;
    if (n <= 0) return;
    for (int q = tid; q < n * MBC; q += NTHR) {
        int i = q >> 4, b = q & 15;
        xc[(lo - k0 + i) * XS + b] = src[(lo - segStart + i) * 16 + b];
    }
}

// ---------------- main kernel: cluster of 2 splits k; 16 batch per cluster ----------------
#define SMEM_FLOATS (MAXTASK*PS + CAT1*XS/2 + 240*XS /*xc sized below*/)
// explicit layout instead:
#define XC_FLOATS   (226 * XS)          // max kh = 224 (+pad)
#define SM_TOTALF   (MAXTASK*PS + XC_FLOATS + INTER_*16 + CMD_*16 + MOTOR_*16 \
                     + OUT_*MOTOR_ + OUT_ + INTER_*4 + CMD_*4 + MOTOR_*4)
#define SMEM_BYTES  (SM_TOTALF * 4)

__global__ void __launch_bounds__(NTHR)
__cluster_dims__(CSIZE, 1, 1)
main_kernel(Params P) {
    extern __shared__ float sm[];
    float* part  = sm;                           // 1076*20
    float* xc    = part + MAXTASK * PS;          // 226*20
    float* h0    = xc + XC_FLOATS;               // 269*16
    float* h1    = h0 + INTER_ * 16;             // 179*16
    float* h2    = h1 + CMD_ * 16;               // 64*16
    float* fcw   = h2 + MOTOR_ * 16;             // 64*64 ([m][o])
    float* fcb   = fcw + OUT_ * MOTOR_;          // 64
    float* bias0 = fcb + OUT_;                   // 269*4
    float* bias1 = bias0 + INTER_ * 4;           // 179*4
    float* bias2 = bias1 + CMD_ * 4;             // 64*4

    const int tid  = threadIdx.x;
    const int grp  = blockIdx.x >> 1;
    const int rank = blockIdx.x & 1;
    const int b0   = grp * MBC;

    float* exMy = g_ex + (size_t)blockIdx.x * EXSZ;
    const float* exPeer = g_ex + (size_t)(blockIdx.x ^ 1) * EXSZ;

    // per-rank k ranges
    const int k00 = (CAT0 * rank) / 2, k01 = (CAT0 * (rank + 1)) / 2, kh0 = k01 - k00;
    const int k10 = (CAT1 * rank) / 2, k11 = (CAT1 * (rank + 1)) / 2, kh1 = k11 - k10;
    const int k20 = (CAT2 * rank) / 2, k21 = (CAT2 * (rank + 1)) / 2, kh2 = k21 - k20;

    // one-time staging
    for (int q = tid; q < INTER_ * 4; q += NTHR) bias0[q] = P.b0[q & 3][q >> 2];
    for (int q = tid; q < CMD_ * 4; q += NTHR)   bias1[q] = P.b1[q & 3][q >> 2];
    for (int q = tid; q < MOTOR_ * 4; q += NTHR) bias2[q] = P.b2[q & 3][q >> 2];
    for (int q = tid; q < OUT_ * MOTOR_; q += NTHR) {
        int m = q >> 6, o = q & 63;
        fcw[m * OUT_ + o] = P.fc_w[o * MOTOR_ + m];
    }
    if (tid < OUT_) fcb[tid] = P.fc_b[tid];
    for (int q = tid; q < INTER_ * MBC; q += NTHR) {
        int i = q >> 4, b = q & 15;
        h0[q] = P.hidden[(size_t)(b0 + b) * UNITS_ + i];
    }
    for (int q = tid; q < CMD_ * MBC; q += NTHR) {
        int i = q >> 4, b = q & 15;
        h1[q] = P.hidden[(size_t)(b0 + b) * UNITS_ + INTER_ + i];
    }
    for (int q = tid; q < MOTOR_ * MBC; q += NTHR) {
        int i = q >> 4, b = q & 15;
        h2[q] = P.hidden[(size_t)(b0 + b) * UNITS_ + INTER_ + CMD_ + i];
    }
    __syncthreads();

    for (int t = 0; t < T_; ++t) {
        // ---- layer 0: input = [x_t (0..128), h0 (128..397)] ----
        {
            int xe = min(k01, DIN_);
            int cnt = xe - k00;
            if (cnt > 0) {
                for (int q = tid; q < cnt * MBC; q += NTHR) {
                    int b = q / cnt, kk = q - b * cnt;
                    xc[(k00 + kk - k00) * XS + b] =
                        P.x[((size_t)(b0 + b) * T_ + t) * DIN_ + k00 + kk];
                }
            }
            stage_h(xc, k00, max(k00, DIN_), k01, DIN_, h0, tid);
        }
        __syncthreads();
        gates<INTER_, KC0>((const float4*)g_wt0, xc, part, k00, kh0, tid);
        __syncthreads();
        phaseA<INTER_, KC0>(part, exMy + EX_L0, tid);
        CLUSTER_ARRIVE(); CLUSTER_WAIT();
        phaseB<INTER_, KC0>(part, exPeer + EX_L0, bias0, h0, tid);
        __syncthreads();

        // ---- layer 1: input = [n0 (0..269), h1 (269..448)] ----
        stage_h(xc, k10, k10, min(k11, INTER_), 0, h0, tid);
        stage_h(xc, k10, max(k10, INTER_), k11, INTER_, h1, tid);
        __syncthreads();
        gates<CMD_, KC1>((const float4*)g_wt1, xc, part, k10, kh1, tid);
        __syncthreads();
        phaseA<CMD_, KC1>(part, exMy + EX_L1, tid);
        CLUSTER_ARRIVE(); CLUSTER_WAIT();
        phaseB<CMD_, KC1>(part, exPeer + EX_L1, bias1, h1, tid);
        __syncthreads();

        // ---- layer 2: input = [n1 (0..179), h2 (179..243)] ----
        stage_h(xc, k20, k20, min(k21, CMD_), 0, h1, tid);
        stage_h(xc, k20, max(k20, CMD_), k21, CMD_, h2, tid);
        __syncthreads();
        gates<MOTOR_, KC2>((const float4*)g_wt2, xc, part, k20, kh2, tid);
        __syncthreads();
        phaseA<MOTOR_, KC2>(part, exMy + EX_L2, tid);
        CLUSTER_ARRIVE(); CLUSTER_WAIT();
        phaseB<MOTOR_, KC2>(part, exPeer + EX_L2, bias2, h2, tid);
        __syncthreads();

        // ---- output head: rank-split batch halves ----
        for (int q = tid; q < 8 * OUT_; q += NTHR) {
            int b = rank * 8 + (q >> 6), o = q & 63;
            float acc = fcb[o];
#pragma unroll
            for (int m = 0; m < MOTOR_; ++m)
                acc += h2[m * 16 + b] * fcw[m * OUT_ + o];
            P.out[((size_t)(b0 + b) * T_ + t) * OUT_ + o] = acc;
        }
        __syncthreads();
    }

    // ---- final hidden state (rank-split batch halves) ----
    size_t hoff = (size_t)B_ * T_ * OUT_;
    for (int q = tid; q < INTER_ * 8; q += NTHR) {
        int i = q >> 3, b = rank * 8 + (q & 7);
        P.out[hoff + (size_t)(b0 + b) * UNITS_ + i] = h0[i * 16 + b];
    }
    for (int q = tid; q < CMD_ * 8; q += NTHR) {
        int i = q >> 3, b = rank * 8 + (q & 7);
        P.out[hoff + (size_t)(b0 + b) * UNITS_ + INTER_ + i] = h1[i * 16 + b];
    }
    for (int q = tid; q < MOTOR_ * 8; q += NTHR) {
        int i = q >> 3, b = rank * 8 + (q & 7);
        P.out[hoff + (size_t)(b0 + b) * UNITS_ + INTER_ + CMD_ + i] = h2[i * 16 + b];
    }
}

// ---------------- launch ----------------
extern "C" void kernel_launch(void* const* d_in, const int* in_sizes, int n_in,
                              void* d_out, int out_size) {
    (void)in_sizes; (void)n_in; (void)out_size;
    Params P;
    P.x      = (const float*)d_in[0];
    P.hidden = (const float*)d_in[1];
    P.mask0  = d_in[2];
    P.mask1  = d_in[3];
    P.mask2  = d_in[4];
    const float** wp[3] = { P.w0, P.w1, P.w2 };
    const float** bp[3] = { P.b0, P.b1, P.b2 };
    int idx = 5;
    for (int l = 0; l < 3; ++l) {
        for (int g = 0; g < 4; ++g) {
            wp[l][g] = (const float*)d_in[idx++];
            bp[l][g] = (const float*)d_in[idx++];
        }
    }
    P.fc_w = (const float*)d_in[idx++];
    P.fc_b = (const float*)d_in[idx++];
    P.out  = (float*)d_out;

    cudaFuncSetAttribute(main_kernel, cudaFuncAttributeMaxDynamicSharedMemorySize,
                         SMEM_BYTES);

    prep_kernel<<<(PTOT_ + 255) / 256, 256>>>(P);
    main_kernel<<<NBLK, NTHR, SMEM_BYTES>>>(P);
}

// round 5
// speedup vs baseline: 1.6667x; 1.6667x over previous
#include <cuda_runtime.h>
#include <math.h>

// ---------------- problem constants ----------------
#define B_      1024
#define T_      256
#define DIN_    128
#define INTER_  269
#define CMD_    179
#define MOTOR_  64
#define OUT_    64
#define UNITS_  512
#define CAT0    397
#define CAT1    448
#define CAT2    243

#define MBT     16                 // batch rows per team (cluster of 2)
#define NBLK    128                // 64 teams x 2
#define NTHR    544                // 17 warps; single-round tasks
#define PSTR    26                 // partial slot stride (floats, 8B aligned)

// X buffer rows: [x_t | h0 | h1 | h2], each row = 16 batch floats.
#define XR_X    0
#define XR_H0   128
#define XR_H1   397
#define XR_H2   576
#define XROWS   640

#define P0_ (CAT0 * INTER_)
#define P1_ (CAT1 * CMD_)
#define P2_ (CAT2 * MOTOR_)
#define PTOT_ (P0_ + P1_ + P2_)

// ---------------- device scratch ----------------
__device__ __align__(16) float2 g_w12_0[P0_];
__device__ __align__(16) float  g_wab_0[P0_];
__device__ __align__(16) float2 g_w12_1[P1_];
__device__ __align__(16) float  g_wab_1[P1_];
__device__ __align__(16) float2 g_w12_2[P2_];
__device__ __align__(16) float  g_wab_2[P2_];

struct Params {
    const float* x;
    const float* hidden;
    const void*  mask0;
    const void*  mask1;
    const void*  mask2;
    const float* w0[4]; const float* b0[4];   // ff1, ff2, ta, tb
    const float* w1[4]; const float* b1[4];
    const float* w2[4]; const float* b2[4];
    const float* fc_w;  const float* fc_b;
    float* out;
};

// ---------------- mask helper ----------------
__device__ __forceinline__ float mask_val(const void* mp, int mode, int e) {
    if (mode == 0) return ((const unsigned char*)mp)[e] ? 1.0f : 0.0f;
    if (mode == 1) return ((const int*)mp)[e] ? 1.0f : 0.0f;
    return (((const float*)mp)[e] != 0.0f) ? 1.0f : 0.0f;
}

// ---------------- prep: sniff mask dtype + folded/masked/transposed weights ----------------
// w12[k*NH + j] = {ff1*m, ff2*m};  wab[k*NH + j] = ta + tb   (ts == 1.0 fold)
__global__ void prep_kernel(Params P) {
    __shared__ int smode[3];
    {
        int w = threadIdx.x >> 5, lane = threadIdx.x & 31;
        if (w < 3) {
            const unsigned char* p = (const unsigned char*)
                (w == 0 ? P.mask0 : (w == 1 ? P.mask1 : P.mask2));
            int nz = 0, gt = 0;
            for (int i = lane; i < 4096; i += 32) {
                unsigned char v = p[i];
                nz += (v != 0);
                gt |= (v > 1);
            }
            nz = __reduce_add_sync(0xffffffffu, nz);
            gt = __reduce_or_sync(0xffffffffu, gt);
            if (lane == 0) smode[w] = gt ? 2 : (nz > 2048 ? 0 : 1);
        }
    }
    __syncthreads();

    int p = blockIdx.x * blockDim.x + threadIdx.x;
    if (p >= PTOT_) return;

    int NH, CATL, local, mode;
    float2* w12; float* wab;
    const float* const* ws;
    const void* mp;
    if (p < P0_) {
        local = p; NH = INTER_; CATL = CAT0;
        w12 = g_w12_0; wab = g_wab_0; ws = P.w0; mp = P.mask0; mode = smode[0];
    } else if (p < P0_ + P1_) {
        local = p - P0_; NH = CMD_; CATL = CAT1;
        w12 = g_w12_1; wab = g_wab_1; ws = P.w1; mp = P.mask1; mode = smode[1];
    } else {
        local = p - P0_ - P1_; NH = MOTOR_; CATL = CAT2;
        w12 = g_w12_2; wab = g_wab_2; ws = P.w2; mp = P.mask2; mode = smode[2];
    }
    int k = local / NH;
    int j = local - k * NH;
    int we = j * CATL + k;
    float m = mask_val(mp, mode, we);
    float2 v;
    v.x = ws[0][we] * m;
    v.y = ws[1][we] * m;
    w12[local] = v;
    wab[local] = ws[2][we] + ws[3][we];
}

// ---------------- asm helpers ----------------
__device__ __forceinline__ unsigned long long pack2(float w) {
    unsigned long long r;
    asm("mov.b64 %0, {%1, %1};" : "=l"(r) : "f"(w));
    return r;
}
#define FFMA2(acc, w2, x2) \
    asm("fma.rn.f32x2 %0, %1, %2, %0;" : "+l"(acc) : "l"(w2), "l"(x2))

__device__ __forceinline__ unsigned s2u(const void* p) {
    unsigned a;
    asm("{ .reg .u64 t; cvta.to.shared.u64 t, %1; cvt.u32.u64 %0, t; }"
        : "=r"(a) : "l"(p));
    return a;
}
__device__ __forceinline__ void st_peer(unsigned laddr, int peer, float v) {
    unsigned ra;
    asm("mapa.shared::cluster.u32 %0, %1, %2;" : "=r"(ra) : "r"(laddr), "r"(peer));
    asm volatile("st.shared::cluster.f32 [%0], %1;" :: "r"(ra), "f"(v) : "memory");
}
__device__ __forceinline__ unsigned my_rank() {
    unsigned r; asm("mov.u32 %0, %%cluster_ctarank;" : "=r"(r)); return r;
}
#define CLUSTER_ARRIVE() asm volatile("barrier.cluster.arrive.aligned;" ::: "memory")
#define CLUSTER_WAIT()   asm volatile("barrier.cluster.wait.aligned;" ::: "memory")

// ---------------- one layer: gates (my j-slice, full k) + combine + dual write ----------------
template <int CATL, int NH, int KC, int XOFF, int HOFF>
__device__ __forceinline__ void do_layer(const float2* __restrict__ w12,
                                         const float* __restrict__ wab,
                                         const float* __restrict__ bb,
                                         float* __restrict__ X,
                                         float* __restrict__ part,
                                         int jbase, int jlc, int peer, int tid) {
    // gates: task = (jl, bq in {0,1}, kc); tasks = jlc*2*KC <= NTHR (single round)
    const int TASKS = jlc * 2 * KC;
    if (tid < TASKS) {
        int jl = tid % jlc;
        int r  = tid / jlc;
        int bq = r & 1, kc = r >> 1;
        int ka = (CATL * kc) / KC;
        int kb = (CATL * (kc + 1)) / KC;
        int j  = jbase + jl;
        const float2* wp = w12 + (size_t)ka * NH + j;
        const float*  ap = wab + (size_t)ka * NH + j;
        const float*  xp = X + (XOFF + ka) * MBT + bq * 8;

        unsigned long long a[12];
#pragma unroll
        for (int i = 0; i < 12; ++i) a[i] = 0ULL;

#pragma unroll 4
        for (int k = ka; k < kb; ++k) {
            float2 w2 = __ldg(wp); wp += NH;
            float  wa = __ldg(ap); ap += NH;
            ulonglong2 x01 = *(const ulonglong2*)xp;
            ulonglong2 x23 = *(const ulonglong2*)(xp + 4);
            xp += MBT;
            unsigned long long p1 = pack2(w2.x);
            unsigned long long p2 = pack2(w2.y);
            unsigned long long p3 = pack2(wa);
            FFMA2(a[0], p1, x01.x); FFMA2(a[1], p1, x01.y);
            FFMA2(a[2], p1, x23.x); FFMA2(a[3], p1, x23.y);
            FFMA2(a[4], p2, x01.x); FFMA2(a[5], p2, x01.y);
            FFMA2(a[6], p2, x23.x); FFMA2(a[7], p2, x23.y);
            FFMA2(a[8], p3, x01.x); FFMA2(a[9], p3, x01.y);
            FFMA2(a[10], p3, x23.x); FFMA2(a[11], p3, x23.y);
        }
        float* pp = part + tid * PSTR;
#pragma unroll
        for (int g = 0; g < 3; ++g)
#pragma unroll
            for (int q = 0; q < 4; ++q)
                *(unsigned long long*)(pp + g * 8 + q * 2) = a[g * 4 + q];
    }
    __syncthreads();          // partials complete; local X reads done
    CLUSTER_ARRIVE();         // publish: done reading my X inputs
    CLUSTER_WAIT();           // peer done reading -> safe to write its h rows

    // combine: h = ff1 + sig(z)*(ff2-ff1); write local X + peer X (DSMEM)
    for (int it = tid; it < jlc * MBT; it += NTHR) {
        int jl = it >> 4, b = it & 15;
        int bq = b >> 3, bl = b & 7;
        float s0 = 0.f, s1 = 0.f, s2 = 0.f;
#pragma unroll
        for (int kc = 0; kc < KC; ++kc) {
            const float* pp = part + ((kc * 2 + bq) * jlc + jl) * PSTR + bl;
            s0 += pp[0]; s1 += pp[8]; s2 += pp[16];
        }
        int j = jbase + jl;
        float ff1 = tanhf(s0 + bb[j * 3 + 0]);
        float ff2 = tanhf(s1 + bb[j * 3 + 1]);
        float z   = s2 + bb[j * 3 + 2];
        float sg  = 1.0f / (1.0f + __expf(-z));
        float h   = ff1 + sg * (ff2 - ff1);
        int idx = (HOFF + j) * MBT + b;
        X[idx] = h;
        st_peer(s2u(&X[idx]), peer, h);
    }
    __syncthreads();
    CLUSTER_ARRIVE();         // my h writes (incl. peer DSMEM) done
    CLUSTER_WAIT();           // peer's h writes into my X visible
}

// ---------------- main kernel ----------------
#define SM_TOTALF (XROWS * MBT + NTHR * PSTR + (INTER_ + CMD_ + MOTOR_) * 3 \
                   + OUT_ * MOTOR_ + OUT_)
#define SMEM_BYTES (SM_TOTALF * 4)

__global__ void __launch_bounds__(NTHR)
__cluster_dims__(2, 1, 1)
main_kernel(Params P) {
    extern __shared__ float sm[];
    float* X    = sm;                                 // 640*16
    float* part = X + XROWS * MBT;                    // 544*26
    float* bb   = part + NTHR * PSTR;                 // 512*3
    float* fcw  = bb + (INTER_ + CMD_ + MOTOR_) * 3;  // 64*64 [m][o]
    float* fcb  = fcw + OUT_ * MOTOR_;                // 64

    const int tid  = threadIdx.x;
    const int team = blockIdx.x >> 1;
    const int rank = (int)my_rank();
    const int peer = rank ^ 1;
    const int b0   = team * MBT;

    // j slices per rank
    const int jb0 = rank * 135, jl0 = rank ? (INTER_ - 135) : 135;   // 135/134
    const int jb1 = rank * 90,  jl1 = rank ? (CMD_ - 90)   : 90;     // 90/89
    const int jb2 = rank * 32,  jl2 = 32;

    float* bb0 = bb;
    float* bb1 = bb + INTER_ * 3;
    float* bb2 = bb + (INTER_ + CMD_) * 3;
    for (int q = tid; q < INTER_ * 3; q += NTHR) {
        int j = q / 3, g = q - j * 3;
        bb0[q] = (g == 0) ? P.b0[0][j] : (g == 1) ? P.b0[1][j] : (P.b0[2][j] + P.b0[3][j]);
    }
    for (int q = tid; q < CMD_ * 3; q += NTHR) {
        int j = q / 3, g = q - j * 3;
        bb1[q] = (g == 0) ? P.b1[0][j] : (g == 1) ? P.b1[1][j] : (P.b1[2][j] + P.b1[3][j]);
    }
    for (int q = tid; q < MOTOR_ * 3; q += NTHR) {
        int j = q / 3, g = q - j * 3;
        bb2[q] = (g == 0) ? P.b2[0][j] : (g == 1) ? P.b2[1][j] : (P.b2[2][j] + P.b2[3][j]);
    }
    for (int q = tid; q < OUT_ * MOTOR_; q += NTHR) {
        int m = q >> 6, o = q & 63;
        fcw[m * OUT_ + o] = P.fc_w[o * MOTOR_ + m];
    }
    if (tid < OUT_) fcb[tid] = P.fc_b[tid];
    // initial hidden: both CTAs stage full 16-batch state
    for (int q = tid; q < UNITS_ * MBT; q += NTHR) {
        int u = q >> 4, b = q & 15;
        X[(XR_H0 + u) * MBT + b] = P.hidden[(size_t)(b0 + b) * UNITS_ + u];
    }
    __syncthreads();

    for (int t = 0; t < T_; ++t) {
        // stage x_t into X rows [0,128)
        for (int q = tid; q < DIN_ * MBT; q += NTHR) {
            int b = q >> 7, k = q & 127;
            X[(XR_X + k) * MBT + b] = P.x[((size_t)(b0 + b) * T_ + t) * DIN_ + k];
        }
        __syncthreads();

        do_layer<CAT0, INTER_, 2, XR_X,  XR_H0>(g_w12_0, g_wab_0, bb0, X, part, jb0, jl0, peer, tid);
        do_layer<CAT1, CMD_,   3, XR_H0, XR_H1>(g_w12_1, g_wab_1, bb1, X, part, jb1, jl1, peer, tid);
        do_layer<CAT2, MOTOR_, 8, XR_H1, XR_H2>(g_w12_2, g_wab_2, bb2, X, part, jb2, jl2, peer, tid);

        // output head: this CTA writes its 8 batches (rank half)
        for (int q = tid; q < 8 * OUT_; q += NTHR) {
            int b = rank * 8 + (q >> 6), o = q & 63;
            float acc = fcb[o];
#pragma unroll
            for (int m = 0; m < MOTOR_; ++m)
                acc += X[(XR_H2 + m) * MBT + b] * fcw[m * OUT_ + o];
            P.out[((size_t)(b0 + b) * T_ + t) * OUT_ + o] = acc;
        }
        __syncthreads();
    }

    // final hidden state: rows [128,640) of X == concat(h0,h1,h2); my 8 batches
    size_t hoff = (size_t)B_ * T_ * OUT_;
    for (int q = tid; q < 8 * UNITS_; q += NTHR) {
        int b = rank * 8 + (q >> 9);
        int u = q & 511;
        P.out[hoff + (size_t)(b0 + b) * UNITS_ + u] = X[(XR_H0 + u) * MBT + b];
    }
    CLUSTER_ARRIVE();
    CLUSTER_WAIT();
}

// ---------------- launch ----------------
extern "C" void kernel_launch(void* const* d_in, const int* in_sizes, int n_in,
                              void* d_out, int out_size) {
    (void)in_sizes; (void)n_in; (void)out_size;
    Params P;
    P.x      = (const float*)d_in[0];
    P.hidden = (const float*)d_in[1];
    P.mask0  = d_in[2];
    P.mask1  = d_in[3];
    P.mask2  = d_in[4];
    const float** wp[3] = { P.w0, P.w1, P.w2 };
    const float** bp[3] = { P.b0, P.b1, P.b2 };
    int idx = 5;
    for (int l = 0; l < 3; ++l) {
        for (int g = 0; g < 4; ++g) {
            wp[l][g] = (const float*)d_in[idx++];
            bp[l][g] = (const float*)d_in[idx++];
        }
    }
    P.fc_w = (const float*)d_in[idx++];
    P.fc_b = (const float*)d_in[idx++];
    P.out  = (float*)d_out;

    cudaFuncSetAttribute(main_kernel, cudaFuncAttributeMaxDynamicSharedMemorySize,
                         SMEM_BYTES);

    prep_kernel<<<(PTOT_ + 255) / 256, 256>>>(P);
    main_kernel<<<NBLK, NTHR, SMEM_BYTES>>>(P);
}